// round 10
// baseline (speedup 1.0000x reference)
#include <cuda_runtime.h>
#include <cuda_fp16.h>
#include <cstdint>

#define DM 1024
#define NH 16
#define HD 64
#define SQ 2048
#define BB 4
#define MT (BB*SQ)   // 8192 rows total

// Scratch (no allocations allowed -> __device__ globals). All fp16.
__device__ __half g_X [(size_t)MT * DM];
__device__ __half g_Wt[(size_t)4 * DM * DM];     // Wq*log2e/8, Wk, Wv, Wo
__device__ __half g_Q [(size_t)MT * DM];         // q*log2e/8
__device__ __half g_K [(size_t)MT * DM];
__device__ __half g_Vt[(size_t)MT * DM];         // v^T per (b,h): [64][SQ]
__device__ __half g_C [(size_t)MT * DM];         // ctx

#define LOG2E 1.4426950408889634f

// ---------------------------------------------------------------------------
// helpers
// ---------------------------------------------------------------------------
__device__ __forceinline__ float ex2(float x)
{
    float y;
    asm("ex2.approx.ftz.f32 %0, %1;" : "=f"(y) : "f"(x));
    return y;
}
__device__ __forceinline__ void mma_f16(float c[4], const unsigned a[4],
                                        const unsigned* b)
{
    asm volatile(
        "mma.sync.aligned.m16n8k16.row.col.f32.f16.f16.f32 "
        "{%0,%1,%2,%3},{%4,%5,%6,%7},{%8,%9},{%0,%1,%2,%3};"
        : "+f"(c[0]), "+f"(c[1]), "+f"(c[2]), "+f"(c[3])
        : "r"(a[0]), "r"(a[1]), "r"(a[2]), "r"(a[3]), "r"(b[0]), "r"(b[1]));
}
__device__ __forceinline__ void ldsm4(unsigned r[4], const __half* p)
{
    unsigned a = (unsigned)__cvta_generic_to_shared(p);
    asm volatile("ldmatrix.sync.aligned.m8n8.x4.shared.b16 {%0,%1,%2,%3}, [%4];"
                 : "=r"(r[0]), "=r"(r[1]), "=r"(r[2]), "=r"(r[3]) : "r"(a));
}
__device__ __forceinline__ void cpa16(void* smem_dst, const void* gsrc)
{
    unsigned s = (unsigned)__cvta_generic_to_shared(smem_dst);
    asm volatile("cp.async.cg.shared.global [%0], [%1], 16;\n" :: "r"(s), "l"(gsrc));
}
#define CPC()  asm volatile("cp.async.commit_group;\n")
#define CPW1() asm volatile("cp.async.wait_group 1;\n")

// ---------------------------------------------------------------------------
// prepass: fp32 -> fp16 (Wq scaled by log2e/8)
// ---------------------------------------------------------------------------
__global__ void prep_kernel(const float* __restrict__ x,
                            const float* __restrict__ Wq,
                            const float* __restrict__ Wk,
                            const float* __restrict__ Wv,
                            const float* __restrict__ Wo)
{
    const int sel = blockIdx.y;
    const float* src; __half* dst; size_t n; float sc = 1.f;
    switch (sel) {
        case 0: src = x;  dst = g_X;               n = (size_t)MT * DM; break;
        case 1: src = Wq; dst = g_Wt;              n = (size_t)DM * DM;
                sc = 0.125f * LOG2E; break;
        case 2: src = Wk; dst = g_Wt + (size_t)DM*DM;   n = (size_t)DM * DM; break;
        case 3: src = Wv; dst = g_Wt + (size_t)2*DM*DM; n = (size_t)DM * DM; break;
        default:src = Wo; dst = g_Wt + (size_t)3*DM*DM; n = (size_t)DM * DM; break;
    }
    const size_t i = ((size_t)blockIdx.x * 256 + threadIdx.x) * 4;
    if (i < n) {
        float4 v = *(const float4*)&src[i];
        *(__half2*)&dst[i]     = __floats2half2_rn(v.x * sc, v.y * sc);
        *(__half2*)&dst[i + 2] = __floats2half2_rn(v.z * sc, v.w * sc);
    }
}

// ---------------------------------------------------------------------------
// FP16 TC GEMM: C[M,N] = A[M,K] @ W[N,K]^T (+bias), fp32 accum.
// 256x128 CTA tile, 8 warps x (64x64), K-chunk 64 halves, double-buffered,
// ldmatrix fragment loads. PAD=72 halves -> LDSM conflict-free.
// mode: 0 = fp16 out (q/k), 1 = fp32 + bias (final), 2 = per-head transposed V
// ---------------------------------------------------------------------------
#define KT 64
#define PAD 72
#define ASTG (256 * PAD)
#define BSTG (128 * PAD)
#define GEMM_SMEM_BYTES (2 * (ASTG + BSTG) * 2)   // 110592 B

__device__ __forceinline__ void gemm_stage(__half* smg, int s,
                                           const __half* __restrict__ A,
                                           const __half* __restrict__ W,
                                           int m0, int n0, int k0, int tid)
{
    __half* As = smg + s * ASTG;
    __half* Bs = smg + 2 * ASTG + s * BSTG;
#pragma unroll
    for (int rep = 0; rep < 8; rep++) {
        const int t = tid + rep * 256;        // 0..2047
        const int row = t >> 3;
        const int seg = (t & 7) * 8;
        cpa16(&As[row * PAD + seg], &A[(size_t)(m0 + row) * DM + k0 + seg]);
    }
#pragma unroll
    for (int rep = 0; rep < 4; rep++) {
        const int t = tid + rep * 256;        // 0..1023
        const int row = t >> 3;
        const int seg = (t & 7) * 8;
        cpa16(&Bs[row * PAD + seg], &W[(size_t)(n0 + row) * DM + k0 + seg]);
    }
}

__device__ __forceinline__ void gemm256_tc(const __half* __restrict__ A,
                                           const __half* __restrict__ W,
                                           const float* __restrict__ bias,
                                           void* __restrict__ Cout,
                                           int mode)
{
    extern __shared__ __half smg[];

    const int tid  = threadIdx.x;
    const int warp = tid >> 5, lane = tid & 31;
    const int wm = warp >> 1, wn = warp & 1;
    const int lg = lane >> 2, lt = lane & 3;
    const int m0 = blockIdx.y * 256;
    const int n0 = blockIdx.x * 128;

    // per-lane ldmatrix address offsets (halves)
    const int arow = (lane & 7) + ((lane >> 3) & 1) * 8;
    const int acol = (lane >> 4) * 8;
    const int brow = (lane & 7) + (lane >> 4) * 8;
    const int bcol = ((lane >> 3) & 1) * 8;

    float acc[4][8][4];
#pragma unroll
    for (int i = 0; i < 4; i++)
#pragma unroll
        for (int j = 0; j < 8; j++)
#pragma unroll
            for (int e = 0; e < 4; e++) acc[i][j][e] = 0.f;

    gemm_stage(smg, 0, A, W, m0, n0, 0, tid);
    CPC();

    for (int k0 = 0; k0 < DM; k0 += KT) {
        const int cur = (k0 >> 6) & 1;
        __syncthreads();
        if (k0 + KT < DM)
            gemm_stage(smg, cur ^ 1, A, W, m0, n0, k0 + KT, tid);
        CPC();
        CPW1();
        __syncthreads();

        const __half* Ab = smg + cur * ASTG;
        const __half* Bb = smg + 2 * ASTG + cur * BSTG;
#pragma unroll
        for (int ks = 0; ks < 4; ks++) {
            const int c = ks * 16;
            unsigned a[4][4], breg[16];
#pragma unroll
            for (int mt = 0; mt < 4; mt++)
                ldsm4(a[mt], &Ab[(wm * 64 + mt * 16 + arow) * PAD + acol + c]);
#pragma unroll
            for (int nb = 0; nb < 4; nb++)
                ldsm4(&breg[nb * 4],
                      &Bb[(wn * 64 + nb * 16 + brow) * PAD + bcol + c]);
#pragma unroll
            for (int mt = 0; mt < 4; mt++)
#pragma unroll
                for (int nt = 0; nt < 8; nt++)
                    mma_f16(acc[mt][nt], a[mt], &breg[nt * 2]);
        }
    }

    // epilogue
    if (mode == 1) {
        float* C = (float*)Cout;
#pragma unroll
        for (int mt = 0; mt < 4; mt++) {
            const int r0 = m0 + wm * 64 + mt * 16 + lg;
#pragma unroll
            for (int nt = 0; nt < 8; nt++) {
                const int col = n0 + wn * 64 + nt * 8 + 2 * lt;
                const float b0 = bias[col], b1 = bias[col + 1];
                *(float2*)&C[(size_t)r0 * DM + col] =
                    make_float2(acc[mt][nt][0] + b0, acc[mt][nt][1] + b1);
                *(float2*)&C[(size_t)(r0 + 8) * DM + col] =
                    make_float2(acc[mt][nt][2] + b0, acc[mt][nt][3] + b1);
            }
        }
    } else if (mode == 0) {
        __half* C = (__half*)Cout;
#pragma unroll
        for (int mt = 0; mt < 4; mt++) {
            const int r0 = m0 + wm * 64 + mt * 16 + lg;
#pragma unroll
            for (int nt = 0; nt < 8; nt++) {
                const int col = n0 + wn * 64 + nt * 8 + 2 * lt;
                *(__half2*)&C[(size_t)r0 * DM + col] =
                    __floats2half2_rn(acc[mt][nt][0], acc[mt][nt][1]);
                *(__half2*)&C[(size_t)(r0 + 8) * DM + col] =
                    __floats2half2_rn(acc[mt][nt][2], acc[mt][nt][3]);
            }
        }
    } else {
        // V: write transposed per-head [b,h,d,s]
        __half* C = (__half*)Cout;
#pragma unroll
        for (int mt = 0; mt < 4; mt++) {
            const int t0 = m0 + wm * 64 + mt * 16 + lg;
#pragma unroll
            for (int nt = 0; nt < 8; nt++) {
                const int col = n0 + wn * 64 + nt * 8 + 2 * lt;
                const int h = col >> 6, d = col & 63;
#pragma unroll
                for (int e = 0; e < 4; e++) {
                    const int t = t0 + (e >> 1) * 8;
                    const int dd = d + (e & 1);
                    const int b = t >> 11, s = t & 2047;
                    C[((size_t)(b * NH + h) * HD + dd) * SQ + s] =
                        __float2half(acc[mt][nt][e]);
                }
            }
        }
    }
}

__global__ __launch_bounds__(256, 1) void qkv_gemm_kernel()
{
    const __half* W; __half* C; int mode;
    if (blockIdx.z == 0)      { W = g_Wt;                   C = g_Q;  mode = 0; }
    else if (blockIdx.z == 1) { W = g_Wt + (size_t)DM*DM;   C = g_K;  mode = 0; }
    else                      { W = g_Wt + (size_t)2*DM*DM; C = g_Vt; mode = 2; }
    gemm256_tc(g_X, W, nullptr, C, mode);
}

__global__ __launch_bounds__(256, 1) void o_gemm_kernel(
    const float* __restrict__ bo, float* __restrict__ out)
{
    gemm256_tc(g_C, g_Wt + (size_t)3*DM*DM, bo, out, 1);
}

// ---------------------------------------------------------------------------
// Flash attention, FP16 TC + ldmatrix, cp.async double-buffered K/V^T tiles.
// 256 queries per CTA, 8 warps x 32 query rows. log2-domain softmax.
// ---------------------------------------------------------------------------
#define QB 256
#define APAD 72
#define ATILE (64 * APAD)
#define KS_OFF 0
#define VT_OFF (2 * ATILE)                       // 9216
#define PS_OFF (4 * ATILE)                       // 18432
#define ATTN_HALVES (PS_OFF + QB * APAD)         // 36864
#define BS_BYTE_OFF (ATTN_HALVES * 2)            // 73728
#define NBAND (SQ + QB - 1)                      // 2303
#define ATTN_SMEM_BYTES (BS_BYTE_OFF + NBAND * 4 + 16)

__global__ __launch_bounds__(256, 1) void attn_kernel(const float* __restrict__ bt)
{
    extern __shared__ __half sm[];
    __half* Ks = sm + KS_OFF;     // [2][64][APAD] (key, d)
    __half* Vt = sm + VT_OFF;     // [2][64][APAD] (d, key)
    __half* Ps = sm + PS_OFF;     // [QB][APAD]  P / Q staging
    float* bsA = (float*)((char*)sm + BS_BYTE_OFF);   // [NBAND] log2-domain bias

    const int tid  = threadIdx.x;
    const int warp = tid >> 5, lane = tid & 31;
    const int lg = lane >> 2, lt = lane & 3;
    const int bh = blockIdx.y;
    const int b = bh >> 4, h = bh & 15;
    const int q0 = blockIdx.x * QB;

    const __half* gK = g_K  + (size_t)b * SQ * DM + h * HD;
    const __half* gV = g_Vt + (size_t)(b * NH + h) * HD * SQ;

    // per-lane ldmatrix offsets
    const int arow = (lane & 7) + ((lane >> 3) & 1) * 8;
    const int acol = (lane >> 4) * 8;
    const int brow = (lane & 7) + (lane >> 4) * 8;
    const int bcol = ((lane >> 3) & 1) * 8;

    for (int j = tid; j < NBAND; j += 256)
        bsA[j] = bt[(size_t)(q0 + j) * NH + h] * LOG2E;

    // stage Q row tid (64 halves = 8 x 16B)
    {
        const __half* src = g_Q + (size_t)(b * SQ + q0 + tid) * DM + h * HD;
#pragma unroll
        for (int rep = 0; rep < 8; rep++)
            *(uint4*)&Ps[tid * APAD + rep * 8] = *(const uint4*)&src[rep * 8];
    }
    __syncwarp();

    // persistent Q fragments: 2 m-tiles x 4 k16-steps (ldmatrix)
    unsigned qf[2][4][4];
#pragma unroll
    for (int mt = 0; mt < 2; mt++)
#pragma unroll
        for (int ks = 0; ks < 4; ks++)
            ldsm4(qf[mt][ks],
                  &Ps[(warp * 32 + mt * 16 + arow) * APAD + acol + ks * 16]);
    __syncwarp();

    // prefetch tile 0 (64 rows x 8 segs per matrix = 512 segs each)
    {
#pragma unroll
        for (int rep = 0; rep < 2; rep++) {
            const int t = tid + rep * 256;    // 0..511
            const int r = t >> 3;
            const int c = (t & 7) * 8;
            cpa16(&Ks[r * APAD + c], &gK[(size_t)r * DM + c]);
            cpa16(&Vt[r * APAD + c], &gV[(size_t)r * SQ + c]);
        }
        CPC();
    }

    float mA[2] = {-1e30f, -1e30f}, mB[2] = {-1e30f, -1e30f};
    float lA[2] = {0.f, 0.f},       lB[2] = {0.f, 0.f};
    float o[2][8][4];
#pragma unroll
    for (int mt = 0; mt < 2; mt++)
#pragma unroll
        for (int nt = 0; nt < 8; nt++)
#pragma unroll
            for (int e = 0; e < 4; e++) o[mt][nt][e] = 0.f;

    for (int k0 = 0, t = 0; k0 < SQ; k0 += 64, t++) {
        const int cur = t & 1;
        __syncthreads();
        if (k0 + 64 < SQ) {
            __half* Kn = Ks + (cur ^ 1) * ATILE;
            __half* Vn = Vt + (cur ^ 1) * ATILE;
#pragma unroll
            for (int rep = 0; rep < 2; rep++) {
                const int tt = tid + rep * 256;
                const int r = tt >> 3;
                const int c = (tt & 7) * 8;
                cpa16(&Kn[r * APAD + c], &gK[(size_t)(k0 + 64 + r) * DM + c]);
                cpa16(&Vn[r * APAD + c], &gV[(size_t)r * SQ + k0 + 64 + c]);
            }
        }
        CPC();
        CPW1();
        __syncthreads();

        const __half* Kb = Ks + cur * ATILE;
        const __half* Vb = Vt + cur * ATILE;

        // ---- S = Q' @ K^T (log2 domain)
        float s[2][8][4];
#pragma unroll
        for (int mt = 0; mt < 2; mt++)
#pragma unroll
            for (int nt = 0; nt < 8; nt++)
#pragma unroll
                for (int e = 0; e < 4; e++) s[mt][nt][e] = 0.f;
#pragma unroll
        for (int ks = 0; ks < 4; ks++) {
            const int c = ks * 16;
            unsigned breg[16];
#pragma unroll
            for (int nb = 0; nb < 4; nb++)
                ldsm4(&breg[nb * 4], &Kb[(nb * 16 + brow) * APAD + bcol + c]);
#pragma unroll
            for (int nt = 0; nt < 8; nt++) {
                mma_f16(s[0][nt], qf[0][ks], &breg[nt * 2]);
                mma_f16(s[1][nt], qf[1][ks], &breg[nt * 2]);
            }
        }

        // ---- bias + online softmax
#pragma unroll
        for (int mt = 0; mt < 2; mt++) {
            const int rA = warp * 32 + mt * 16 + lg;
            const int rB = rA + 8;
            const int jbA = rA + 2047 - k0;
            const int jbB = rB + 2047 - k0;
            float mxA = -1e30f, mxB = -1e30f;
#pragma unroll
            for (int nt = 0; nt < 8; nt++) {
                const int col = nt * 8 + 2 * lt;
                s[mt][nt][0] += bsA[jbA - col];
                s[mt][nt][1] += bsA[jbA - col - 1];
                s[mt][nt][2] += bsA[jbB - col];
                s[mt][nt][3] += bsA[jbB - col - 1];
                mxA = fmaxf(mxA, fmaxf(s[mt][nt][0], s[mt][nt][1]));
                mxB = fmaxf(mxB, fmaxf(s[mt][nt][2], s[mt][nt][3]));
            }
#pragma unroll
            for (int off = 1; off <= 2; off <<= 1) {
                mxA = fmaxf(mxA, __shfl_xor_sync(0xffffffffu, mxA, off));
                mxB = fmaxf(mxB, __shfl_xor_sync(0xffffffffu, mxB, off));
            }
            const float mnA = fmaxf(mA[mt], mxA);
            const float mnB = fmaxf(mB[mt], mxB);
            const float crA = ex2(mA[mt] - mnA);
            const float crB = ex2(mB[mt] - mnB);
            float sA = 0.f, sB = 0.f;
#pragma unroll
            for (int nt = 0; nt < 8; nt++) {
                s[mt][nt][0] = ex2(s[mt][nt][0] - mnA);
                s[mt][nt][1] = ex2(s[mt][nt][1] - mnA);
                s[mt][nt][2] = ex2(s[mt][nt][2] - mnB);
                s[mt][nt][3] = ex2(s[mt][nt][3] - mnB);
                sA += s[mt][nt][0] + s[mt][nt][1];
                sB += s[mt][nt][2] + s[mt][nt][3];
                const int col = nt * 8 + 2 * lt;
                *(__half2*)&Ps[rA * APAD + col] =
                    __floats2half2_rn(s[mt][nt][0], s[mt][nt][1]);
                *(__half2*)&Ps[rB * APAD + col] =
                    __floats2half2_rn(s[mt][nt][2], s[mt][nt][3]);
            }
#pragma unroll
            for (int off = 1; off <= 2; off <<= 1) {
                sA += __shfl_xor_sync(0xffffffffu, sA, off);
                sB += __shfl_xor_sync(0xffffffffu, sB, off);
            }
            lA[mt] = lA[mt] * crA + sA;
            lB[mt] = lB[mt] * crB + sB;
            mA[mt] = mnA; mB[mt] = mnB;
#pragma unroll
            for (int nt = 0; nt < 8; nt++) {
                o[mt][nt][0] *= crA; o[mt][nt][1] *= crA;
                o[mt][nt][2] *= crB; o[mt][nt][3] *= crB;
            }
        }
        __syncwarp();

        // ---- acc += P @ V
#pragma unroll
        for (int ks = 0; ks < 4; ks++) {
            const int c = ks * 16;
            unsigned pa[2][4], breg[16];
#pragma unroll
            for (int mt = 0; mt < 2; mt++)
                ldsm4(pa[mt],
                      &Ps[(warp * 32 + mt * 16 + arow) * APAD + acol + c]);
#pragma unroll
            for (int nb = 0; nb < 4; nb++)
                ldsm4(&breg[nb * 4], &Vb[(nb * 16 + brow) * APAD + bcol + c]);
#pragma unroll
            for (int nt = 0; nt < 8; nt++) {
                mma_f16(o[0][nt], pa[0], &breg[nt * 2]);
                mma_f16(o[1][nt], pa[1], &breg[nt * 2]);
            }
        }
    }

    // ---- normalize + write ctx [B,S,D] fp16
#pragma unroll
    for (int mt = 0; mt < 2; mt++) {
        const int rA = warp * 32 + mt * 16 + lg;
        const float invA = 1.f / lA[mt];
        const float invB = 1.f / lB[mt];
        __half* dstA = g_C + (size_t)(b * SQ + q0 + rA) * DM + h * HD;
        __half* dstB = g_C + (size_t)(b * SQ + q0 + rA + 8) * DM + h * HD;
#pragma unroll
        for (int nt = 0; nt < 8; nt++) {
            const int col = nt * 8 + 2 * lt;
            *(__half2*)&dstA[col] =
                __floats2half2_rn(o[mt][nt][0] * invA, o[mt][nt][1] * invA);
            *(__half2*)&dstB[col] =
                __floats2half2_rn(o[mt][nt][2] * invB, o[mt][nt][3] * invB);
        }
    }
}

// ---------------------------------------------------------------------------
extern "C" void kernel_launch(void* const* d_in, const int* in_sizes, int n_in,
                              void* d_out, int out_size)
{
    (void)in_sizes; (void)n_in; (void)out_size;
    const float* x   = (const float*)d_in[0];
    const float* Wq  = (const float*)d_in[1];
    const float* Wk  = (const float*)d_in[2];
    const float* Wv  = (const float*)d_in[3];
    const float* Wo  = (const float*)d_in[4];
    const float* bo  = (const float*)d_in[5];
    const float* bt  = (const float*)d_in[6];
    float* out = (float*)d_out;

    // 0) fp16 prepass
    dim3 g0((MT * DM / 4 + 255) / 256, 5);
    prep_kernel<<<g0, 256>>>(x, Wq, Wk, Wv, Wo);

    // 1) QKV projections
    cudaFuncSetAttribute(qkv_gemm_kernel,
                         cudaFuncAttributeMaxDynamicSharedMemorySize,
                         GEMM_SMEM_BYTES);
    dim3 g1(DM / 128, MT / 256, 3);
    qkv_gemm_kernel<<<g1, 256, GEMM_SMEM_BYTES>>>();

    // 2) attention
    cudaFuncSetAttribute(attn_kernel,
                         cudaFuncAttributeMaxDynamicSharedMemorySize,
                         ATTN_SMEM_BYTES);
    dim3 g2(SQ / QB, BB * NH);
    attn_kernel<<<g2, 256, ATTN_SMEM_BYTES>>>(bt);

    // 3) output projection + bias
    cudaFuncSetAttribute(o_gemm_kernel,
                         cudaFuncAttributeMaxDynamicSharedMemorySize,
                         GEMM_SMEM_BYTES);
    dim3 g3(DM / 128, MT / 256);
    o_gemm_kernel<<<g3, 256, GEMM_SMEM_BYTES>>>(bo, out);
}

// round 11
// speedup vs baseline: 1.1666x; 1.1666x over previous
#include <cuda_runtime.h>
#include <cuda_fp16.h>
#include <cstdint>

#define DM 1024
#define NH 16
#define HD 64
#define SQ 2048
#define BB 4
#define MT (BB*SQ)   // 8192 rows total

// Scratch (no allocations allowed -> __device__ globals). All fp16.
__device__ __half g_X [(size_t)MT * DM];
__device__ __half g_Wt[(size_t)4 * DM * DM];     // Wq*log2e/8, Wk, Wv, Wo
__device__ __half g_Q [(size_t)MT * DM];         // q*log2e/8
__device__ __half g_K [(size_t)MT * DM];
__device__ __half g_Vt[(size_t)MT * DM];         // v^T per (b,h): [64][SQ]
__device__ __half g_C [(size_t)MT * DM];         // ctx

#define LOG2E 1.4426950408889634f

// ---------------------------------------------------------------------------
// helpers
// ---------------------------------------------------------------------------
__device__ __forceinline__ float ex2(float x)
{
    float y;
    asm("ex2.approx.ftz.f32 %0, %1;" : "=f"(y) : "f"(x));
    return y;
}
__device__ __forceinline__ void mma_f16(float c[4], const unsigned a[4],
                                        const unsigned* b)
{
    asm volatile(
        "mma.sync.aligned.m16n8k16.row.col.f32.f16.f16.f32 "
        "{%0,%1,%2,%3},{%4,%5,%6,%7},{%8,%9},{%0,%1,%2,%3};"
        : "+f"(c[0]), "+f"(c[1]), "+f"(c[2]), "+f"(c[3])
        : "r"(a[0]), "r"(a[1]), "r"(a[2]), "r"(a[3]), "r"(b[0]), "r"(b[1]));
}
__device__ __forceinline__ void ldsm4(unsigned r[4], const __half* p)
{
    unsigned a = (unsigned)__cvta_generic_to_shared(p);
    asm volatile("ldmatrix.sync.aligned.m8n8.x4.shared.b16 {%0,%1,%2,%3}, [%4];"
                 : "=r"(r[0]), "=r"(r[1]), "=r"(r[2]), "=r"(r[3]) : "r"(a));
}
__device__ __forceinline__ void cpa16(void* smem_dst, const void* gsrc)
{
    unsigned s = (unsigned)__cvta_generic_to_shared(smem_dst);
    asm volatile("cp.async.cg.shared.global [%0], [%1], 16;\n" :: "r"(s), "l"(gsrc));
}
#define CPC()  asm volatile("cp.async.commit_group;\n")
#define CPW1() asm volatile("cp.async.wait_group 1;\n")

// ---------------------------------------------------------------------------
// prepass: fp32 -> fp16 (Wq scaled by log2e/8)
// ---------------------------------------------------------------------------
__global__ void prep_kernel(const float* __restrict__ x,
                            const float* __restrict__ Wq,
                            const float* __restrict__ Wk,
                            const float* __restrict__ Wv,
                            const float* __restrict__ Wo)
{
    const int sel = blockIdx.y;
    const float* src; __half* dst; size_t n; float sc = 1.f;
    switch (sel) {
        case 0: src = x;  dst = g_X;               n = (size_t)MT * DM; break;
        case 1: src = Wq; dst = g_Wt;              n = (size_t)DM * DM;
                sc = 0.125f * LOG2E; break;
        case 2: src = Wk; dst = g_Wt + (size_t)DM*DM;   n = (size_t)DM * DM; break;
        case 3: src = Wv; dst = g_Wt + (size_t)2*DM*DM; n = (size_t)DM * DM; break;
        default:src = Wo; dst = g_Wt + (size_t)3*DM*DM; n = (size_t)DM * DM; break;
    }
    const size_t i = ((size_t)blockIdx.x * 256 + threadIdx.x) * 4;
    if (i < n) {
        float4 v = *(const float4*)&src[i];
        *(__half2*)&dst[i]     = __floats2half2_rn(v.x * sc, v.y * sc);
        *(__half2*)&dst[i + 2] = __floats2half2_rn(v.z * sc, v.w * sc);
    }
}

// ---------------------------------------------------------------------------
// FP16 TC GEMM: C[M,N] = A[M,K] @ W[N,K]^T (+bias), fp32 accum.
// 128x128 CTA tile, 4 warps x (64x64), K-chunk 64 halves, double-buffered,
// ldmatrix fragment loads, PAD=72 halves (LDSM conflict-free), 2 CTAs/SM.
// mode: 0 = fp16 out (q/k), 1 = fp32 + bias (final), 2 = per-head transposed V
// ---------------------------------------------------------------------------
#define KT 64
#define PAD 72
#define GSTG (128 * PAD)                      // halves per matrix stage
#define GEMM_SMEM_BYTES (4 * GSTG * 2)        // 73728 B

__device__ __forceinline__ void gemm_stage(__half* As, __half* Bs,
                                           const __half* __restrict__ A,
                                           const __half* __restrict__ W,
                                           int m0, int n0, int k0, int tid)
{
#pragma unroll
    for (int rep = 0; rep < 8; rep++) {
        const int t = tid + rep * 128;        // 0..1023
        const int row = t >> 3;
        const int seg = (t & 7) * 8;          // halves (16B)
        cpa16(&As[row * PAD + seg], &A[(size_t)(m0 + row) * DM + k0 + seg]);
        cpa16(&Bs[row * PAD + seg], &W[(size_t)(n0 + row) * DM + k0 + seg]);
    }
}

__device__ __forceinline__ void gemm128_tc(const __half* __restrict__ A,
                                           const __half* __restrict__ W,
                                           const float* __restrict__ bias,
                                           void* __restrict__ Cout,
                                           int mode)
{
    extern __shared__ __half smg[];
    __half* As = smg;                 // [2][128][PAD]
    __half* Bs = smg + 2 * GSTG;      // [2][128][PAD]

    const int tid  = threadIdx.x;
    const int warp = tid >> 5, lane = tid & 31;
    const int wm = warp >> 1, wn = warp & 1;
    const int lg = lane >> 2, lt = lane & 3;
    const int m0 = blockIdx.y * 128;
    const int n0 = blockIdx.x * 128;

    // per-lane ldmatrix address offsets (halves)
    const int arow = (lane & 7) + ((lane >> 3) & 1) * 8;
    const int acol = (lane >> 4) * 8;
    const int brow = (lane & 7) + (lane >> 4) * 8;
    const int bcol = ((lane >> 3) & 1) * 8;

    float acc[4][8][4];
#pragma unroll
    for (int i = 0; i < 4; i++)
#pragma unroll
        for (int j = 0; j < 8; j++)
#pragma unroll
            for (int e = 0; e < 4; e++) acc[i][j][e] = 0.f;

    gemm_stage(As, Bs, A, W, m0, n0, 0, tid);
    CPC();

    for (int k0 = 0; k0 < DM; k0 += KT) {
        const int cur = (k0 >> 6) & 1;
        __syncthreads();
        if (k0 + KT < DM)
            gemm_stage(As + (cur ^ 1) * GSTG, Bs + (cur ^ 1) * GSTG,
                       A, W, m0, n0, k0 + KT, tid);
        CPC();
        CPW1();
        __syncthreads();

        const __half* Ab = As + cur * GSTG;
        const __half* Bb = Bs + cur * GSTG;
#pragma unroll
        for (int ks = 0; ks < 4; ks++) {
            const int c = ks * 16;
            unsigned a[4][4], breg[16];
#pragma unroll
            for (int mt = 0; mt < 4; mt++)
                ldsm4(a[mt], &Ab[(wm * 64 + mt * 16 + arow) * PAD + acol + c]);
#pragma unroll
            for (int nb = 0; nb < 4; nb++)
                ldsm4(&breg[nb * 4],
                      &Bb[(wn * 64 + nb * 16 + brow) * PAD + bcol + c]);
#pragma unroll
            for (int mt = 0; mt < 4; mt++)
#pragma unroll
                for (int nt = 0; nt < 8; nt++)
                    mma_f16(acc[mt][nt], a[mt], &breg[nt * 2]);
        }
    }

    // epilogue
    if (mode == 1) {
        float* C = (float*)Cout;
#pragma unroll
        for (int mt = 0; mt < 4; mt++) {
            const int r0 = m0 + wm * 64 + mt * 16 + lg;
#pragma unroll
            for (int nt = 0; nt < 8; nt++) {
                const int col = n0 + wn * 64 + nt * 8 + 2 * lt;
                const float b0 = bias[col], b1 = bias[col + 1];
                *(float2*)&C[(size_t)r0 * DM + col] =
                    make_float2(acc[mt][nt][0] + b0, acc[mt][nt][1] + b1);
                *(float2*)&C[(size_t)(r0 + 8) * DM + col] =
                    make_float2(acc[mt][nt][2] + b0, acc[mt][nt][3] + b1);
            }
        }
    } else if (mode == 0) {
        __half* C = (__half*)Cout;
#pragma unroll
        for (int mt = 0; mt < 4; mt++) {
            const int r0 = m0 + wm * 64 + mt * 16 + lg;
#pragma unroll
            for (int nt = 0; nt < 8; nt++) {
                const int col = n0 + wn * 64 + nt * 8 + 2 * lt;
                *(__half2*)&C[(size_t)r0 * DM + col] =
                    __floats2half2_rn(acc[mt][nt][0], acc[mt][nt][1]);
                *(__half2*)&C[(size_t)(r0 + 8) * DM + col] =
                    __floats2half2_rn(acc[mt][nt][2], acc[mt][nt][3]);
            }
        }
    } else {
        // V: write transposed per-head [b,h,d,s]
        __half* C = (__half*)Cout;
#pragma unroll
        for (int mt = 0; mt < 4; mt++) {
            const int t0 = m0 + wm * 64 + mt * 16 + lg;
#pragma unroll
            for (int nt = 0; nt < 8; nt++) {
                const int col = n0 + wn * 64 + nt * 8 + 2 * lt;
                const int h = col >> 6, d = col & 63;
#pragma unroll
                for (int e = 0; e < 4; e++) {
                    const int t = t0 + (e >> 1) * 8;
                    const int dd = d + (e & 1);
                    const int b = t >> 11, s = t & 2047;
                    C[((size_t)(b * NH + h) * HD + dd) * SQ + s] =
                        __float2half(acc[mt][nt][e]);
                }
            }
        }
    }
}

__global__ __launch_bounds__(128, 2) void qkv_gemm_kernel()
{
    const __half* W; __half* C; int mode;
    if (blockIdx.z == 0)      { W = g_Wt;                   C = g_Q;  mode = 0; }
    else if (blockIdx.z == 1) { W = g_Wt + (size_t)DM*DM;   C = g_K;  mode = 0; }
    else                      { W = g_Wt + (size_t)2*DM*DM; C = g_Vt; mode = 2; }
    gemm128_tc(g_X, W, nullptr, C, mode);
}

__global__ __launch_bounds__(128, 2) void o_gemm_kernel(
    const float* __restrict__ bo, float* __restrict__ out)
{
    gemm128_tc(g_C, g_Wt + (size_t)3*DM*DM, bo, out, 1);
}

// ---------------------------------------------------------------------------
// Flash attention, FP16 TC + ldmatrix, cp.async double-buffered K/V^T tiles.
// 128 queries per CTA, 4 warps x 32 query rows. log2-domain softmax.
// ---------------------------------------------------------------------------
#define APAD 72
#define ATILE (64 * APAD)                       // 4608 halves per K/V stage
#define KS_OFF 0
#define VT_OFF (2 * ATILE)                      // 9216
#define PS_OFF (4 * ATILE)                      // 18432
#define ATTN_HALVES (PS_OFF + 128 * APAD)       // 27648
#define BS_BYTE_OFF (ATTN_HALVES * 2)           // 55296
#define ATTN_SMEM_BYTES (BS_BYTE_OFF + 2176 * 4)

__global__ __launch_bounds__(128, 2) void attn_kernel(const float* __restrict__ bt)
{
    extern __shared__ __half sm[];
    __half* Ks = sm + KS_OFF;     // [2][64][APAD] (key, d)
    __half* Vt = sm + VT_OFF;     // [2][64][APAD] (d, key)
    __half* Ps = sm + PS_OFF;     // [128][APAD]  P / Q staging
    float* bsA = (float*)((char*)sm + BS_BYTE_OFF);   // [2175] log2-domain bias

    const int tid  = threadIdx.x;
    const int warp = tid >> 5, lane = tid & 31;
    const int lg = lane >> 2, lt = lane & 3;
    const int bh = blockIdx.y;
    const int b = bh >> 4, h = bh & 15;
    const int q0 = blockIdx.x * 128;

    const __half* gK = g_K  + (size_t)b * SQ * DM + h * HD;
    const __half* gV = g_Vt + (size_t)(b * NH + h) * HD * SQ;

    // per-lane ldmatrix offsets
    const int arow = (lane & 7) + ((lane >> 3) & 1) * 8;
    const int acol = (lane >> 4) * 8;
    const int brow = (lane & 7) + (lane >> 4) * 8;
    const int bcol = ((lane >> 3) & 1) * 8;

    for (int j = tid; j < 2175; j += 128)
        bsA[j] = bt[(size_t)(q0 + j) * NH + h] * LOG2E;

    // stage Q row tid (64 halves = 8 x 16B)
    {
        const __half* src = g_Q + (size_t)(b * SQ + q0 + tid) * DM + h * HD;
#pragma unroll
        for (int rep = 0; rep < 8; rep++)
            *(uint4*)&Ps[tid * APAD + rep * 8] = *(const uint4*)&src[rep * 8];
    }
    __syncwarp();

    // persistent Q fragments: 2 m-tiles x 4 k16-steps (ldmatrix)
    unsigned qf[2][4][4];
#pragma unroll
    for (int mt = 0; mt < 2; mt++)
#pragma unroll
        for (int ks = 0; ks < 4; ks++)
            ldsm4(qf[mt][ks],
                  &Ps[(warp * 32 + mt * 16 + arow) * APAD + acol + ks * 16]);
    __syncwarp();

    // prefetch tile 0 (64 rows x 8 segs per matrix)
    {
#pragma unroll
        for (int rep = 0; rep < 4; rep++) {
            const int t = tid + rep * 128;    // 0..511
            const int r = t >> 3;
            const int c = (t & 7) * 8;
            cpa16(&Ks[r * APAD + c], &gK[(size_t)r * DM + c]);
            cpa16(&Vt[r * APAD + c], &gV[(size_t)r * SQ + c]);
        }
        CPC();
    }

    float mA[2] = {-1e30f, -1e30f}, mB[2] = {-1e30f, -1e30f};
    float lA[2] = {0.f, 0.f},       lB[2] = {0.f, 0.f};
    float o[2][8][4];
#pragma unroll
    for (int mt = 0; mt < 2; mt++)
#pragma unroll
        for (int nt = 0; nt < 8; nt++)
#pragma unroll
            for (int e = 0; e < 4; e++) o[mt][nt][e] = 0.f;

    for (int k0 = 0, t = 0; k0 < SQ; k0 += 64, t++) {
        const int cur = t & 1;
        __syncthreads();
        if (k0 + 64 < SQ) {
            __half* Kn = Ks + (cur ^ 1) * ATILE;
            __half* Vn = Vt + (cur ^ 1) * ATILE;
#pragma unroll
            for (int rep = 0; rep < 4; rep++) {
                const int tt = tid + rep * 128;
                const int r = tt >> 3;
                const int c = (tt & 7) * 8;
                cpa16(&Kn[r * APAD + c], &gK[(size_t)(k0 + 64 + r) * DM + c]);
                cpa16(&Vn[r * APAD + c], &gV[(size_t)r * SQ + k0 + 64 + c]);
            }
        }
        CPC();
        CPW1();
        __syncthreads();

        const __half* Kb = Ks + cur * ATILE;
        const __half* Vb = Vt + cur * ATILE;

        // ---- S = Q' @ K^T (log2 domain)
        float s[2][8][4];
#pragma unroll
        for (int mt = 0; mt < 2; mt++)
#pragma unroll
            for (int nt = 0; nt < 8; nt++)
#pragma unroll
                for (int e = 0; e < 4; e++) s[mt][nt][e] = 0.f;
#pragma unroll
        for (int ks = 0; ks < 4; ks++) {
            const int c = ks * 16;
            unsigned breg[16];
#pragma unroll
            for (int nb = 0; nb < 4; nb++)
                ldsm4(&breg[nb * 4], &Kb[(nb * 16 + brow) * APAD + bcol + c]);
#pragma unroll
            for (int nt = 0; nt < 8; nt++) {
                mma_f16(s[0][nt], qf[0][ks], &breg[nt * 2]);
                mma_f16(s[1][nt], qf[1][ks], &breg[nt * 2]);
            }
        }

        // ---- bias + online softmax
#pragma unroll
        for (int mt = 0; mt < 2; mt++) {
            const int rA = warp * 32 + mt * 16 + lg;
            const int rB = rA + 8;
            const int jbA = rA + 2047 - k0;
            const int jbB = rB + 2047 - k0;
            float mxA = -1e30f, mxB = -1e30f;
#pragma unroll
            for (int nt = 0; nt < 8; nt++) {
                const int col = nt * 8 + 2 * lt;
                s[mt][nt][0] += bsA[jbA - col];
                s[mt][nt][1] += bsA[jbA - col - 1];
                s[mt][nt][2] += bsA[jbB - col];
                s[mt][nt][3] += bsA[jbB - col - 1];
                mxA = fmaxf(mxA, fmaxf(s[mt][nt][0], s[mt][nt][1]));
                mxB = fmaxf(mxB, fmaxf(s[mt][nt][2], s[mt][nt][3]));
            }
#pragma unroll
            for (int off = 1; off <= 2; off <<= 1) {
                mxA = fmaxf(mxA, __shfl_xor_sync(0xffffffffu, mxA, off));
                mxB = fmaxf(mxB, __shfl_xor_sync(0xffffffffu, mxB, off));
            }
            const float mnA = fmaxf(mA[mt], mxA);
            const float mnB = fmaxf(mB[mt], mxB);
            const float crA = ex2(mA[mt] - mnA);
            const float crB = ex2(mB[mt] - mnB);
            float sA = 0.f, sB = 0.f;
#pragma unroll
            for (int nt = 0; nt < 8; nt++) {
                s[mt][nt][0] = ex2(s[mt][nt][0] - mnA);
                s[mt][nt][1] = ex2(s[mt][nt][1] - mnA);
                s[mt][nt][2] = ex2(s[mt][nt][2] - mnB);
                s[mt][nt][3] = ex2(s[mt][nt][3] - mnB);
                sA += s[mt][nt][0] + s[mt][nt][1];
                sB += s[mt][nt][2] + s[mt][nt][3];
                const int col = nt * 8 + 2 * lt;
                *(__half2*)&Ps[rA * APAD + col] =
                    __floats2half2_rn(s[mt][nt][0], s[mt][nt][1]);
                *(__half2*)&Ps[rB * APAD + col] =
                    __floats2half2_rn(s[mt][nt][2], s[mt][nt][3]);
            }
#pragma unroll
            for (int off = 1; off <= 2; off <<= 1) {
                sA += __shfl_xor_sync(0xffffffffu, sA, off);
                sB += __shfl_xor_sync(0xffffffffu, sB, off);
            }
            lA[mt] = lA[mt] * crA + sA;
            lB[mt] = lB[mt] * crB + sB;
            mA[mt] = mnA; mB[mt] = mnB;
#pragma unroll
            for (int nt = 0; nt < 8; nt++) {
                o[mt][nt][0] *= crA; o[mt][nt][1] *= crA;
                o[mt][nt][2] *= crB; o[mt][nt][3] *= crB;
            }
        }
        __syncwarp();

        // ---- acc += P @ V
#pragma unroll
        for (int ks = 0; ks < 4; ks++) {
            const int c = ks * 16;
            unsigned pa[2][4], breg[16];
#pragma unroll
            for (int mt = 0; mt < 2; mt++)
                ldsm4(pa[mt],
                      &Ps[(warp * 32 + mt * 16 + arow) * APAD + acol + c]);
#pragma unroll
            for (int nb = 0; nb < 4; nb++)
                ldsm4(&breg[nb * 4], &Vb[(nb * 16 + brow) * APAD + bcol + c]);
#pragma unroll
            for (int nt = 0; nt < 8; nt++) {
                mma_f16(o[0][nt], pa[0], &breg[nt * 2]);
                mma_f16(o[1][nt], pa[1], &breg[nt * 2]);
            }
        }
    }

    // ---- normalize + write ctx [B,S,D] fp16
#pragma unroll
    for (int mt = 0; mt < 2; mt++) {
        const int rA = warp * 32 + mt * 16 + lg;
        const float invA = 1.f / lA[mt];
        const float invB = 1.f / lB[mt];
        __half* dstA = g_C + (size_t)(b * SQ + q0 + rA) * DM + h * HD;
        __half* dstB = g_C + (size_t)(b * SQ + q0 + rA + 8) * DM + h * HD;
#pragma unroll
        for (int nt = 0; nt < 8; nt++) {
            const int col = nt * 8 + 2 * lt;
            *(__half2*)&dstA[col] =
                __floats2half2_rn(o[mt][nt][0] * invA, o[mt][nt][1] * invA);
            *(__half2*)&dstB[col] =
                __floats2half2_rn(o[mt][nt][2] * invB, o[mt][nt][3] * invB);
        }
    }
}

// ---------------------------------------------------------------------------
extern "C" void kernel_launch(void* const* d_in, const int* in_sizes, int n_in,
                              void* d_out, int out_size)
{
    (void)in_sizes; (void)n_in; (void)out_size;
    const float* x   = (const float*)d_in[0];
    const float* Wq  = (const float*)d_in[1];
    const float* Wk  = (const float*)d_in[2];
    const float* Wv  = (const float*)d_in[3];
    const float* Wo  = (const float*)d_in[4];
    const float* bo  = (const float*)d_in[5];
    const float* bt  = (const float*)d_in[6];
    float* out = (float*)d_out;

    // 0) fp16 prepass
    dim3 g0((MT * DM / 4 + 255) / 256, 5);
    prep_kernel<<<g0, 256>>>(x, Wq, Wk, Wv, Wo);

    // 1) QKV projections
    cudaFuncSetAttribute(qkv_gemm_kernel,
                         cudaFuncAttributeMaxDynamicSharedMemorySize,
                         GEMM_SMEM_BYTES);
    dim3 g1(DM / 128, MT / 128, 3);
    qkv_gemm_kernel<<<g1, 128, GEMM_SMEM_BYTES>>>();

    // 2) attention
    cudaFuncSetAttribute(attn_kernel,
                         cudaFuncAttributeMaxDynamicSharedMemorySize,
                         ATTN_SMEM_BYTES);
    dim3 g2(SQ / 128, BB * NH);
    attn_kernel<<<g2, 128, ATTN_SMEM_BYTES>>>(bt);

    // 3) output projection + bias
    cudaFuncSetAttribute(o_gemm_kernel,
                         cudaFuncAttributeMaxDynamicSharedMemorySize,
                         GEMM_SMEM_BYTES);
    dim3 g3(DM / 128, MT / 128);
    o_gemm_kernel<<<g3, 128, GEMM_SMEM_BYTES>>>(bo, out);
}

// round 12
// speedup vs baseline: 1.2422x; 1.0648x over previous
#include <cuda_runtime.h>
#include <cuda_fp16.h>
#include <cstdint>

#define DM 1024
#define NH 16
#define HD 64
#define SQ 2048
#define BB 4
#define MT (BB*SQ)   // 8192 rows total

// Scratch (no allocations allowed -> __device__ globals). All fp16.
__device__ __half g_X [(size_t)MT * DM];
__device__ __half g_Wt[(size_t)4 * DM * DM];     // Wq*log2e/8, Wk, Wv, Wo
__device__ __half g_Q [(size_t)MT * DM];         // q*log2e/8
__device__ __half g_K [(size_t)MT * DM];
__device__ __half g_Vt[(size_t)MT * DM];         // v^T per (b,h): [64][SQ]
__device__ __half g_C [(size_t)MT * DM];         // ctx

#define LOG2E 1.4426950408889634f

// ---------------------------------------------------------------------------
// helpers
// ---------------------------------------------------------------------------
__device__ __forceinline__ float ex2(float x)
{
    float y;
    asm("ex2.approx.ftz.f32 %0, %1;" : "=f"(y) : "f"(x));
    return y;
}
__device__ __forceinline__ unsigned packh2(float a, float b)
{
    __half2 h = __floats2half2_rn(a, b);
    return *(unsigned*)&h;
}
__device__ __forceinline__ void mma_f16(float c[4], const unsigned a[4],
                                        const unsigned* b)
{
    asm volatile(
        "mma.sync.aligned.m16n8k16.row.col.f32.f16.f16.f32 "
        "{%0,%1,%2,%3},{%4,%5,%6,%7},{%8,%9},{%0,%1,%2,%3};"
        : "+f"(c[0]), "+f"(c[1]), "+f"(c[2]), "+f"(c[3])
        : "r"(a[0]), "r"(a[1]), "r"(a[2]), "r"(a[3]), "r"(b[0]), "r"(b[1]));
}
__device__ __forceinline__ void ldsm4(unsigned r[4], const __half* p)
{
    unsigned a = (unsigned)__cvta_generic_to_shared(p);
    asm volatile("ldmatrix.sync.aligned.m8n8.x4.shared.b16 {%0,%1,%2,%3}, [%4];"
                 : "=r"(r[0]), "=r"(r[1]), "=r"(r[2]), "=r"(r[3]) : "r"(a));
}
__device__ __forceinline__ void cpa16(void* smem_dst, const void* gsrc)
{
    unsigned s = (unsigned)__cvta_generic_to_shared(smem_dst);
    asm volatile("cp.async.cg.shared.global [%0], [%1], 16;\n" :: "r"(s), "l"(gsrc));
}
#define CPC()  asm volatile("cp.async.commit_group;\n")
#define CPW1() asm volatile("cp.async.wait_group 1;\n")

// ---------------------------------------------------------------------------
// prepass: fp32 -> fp16 (Wq scaled by log2e/8)
// ---------------------------------------------------------------------------
__global__ void prep_kernel(const float* __restrict__ x,
                            const float* __restrict__ Wq,
                            const float* __restrict__ Wk,
                            const float* __restrict__ Wv,
                            const float* __restrict__ Wo)
{
    const int sel = blockIdx.y;
    const float* src; __half* dst; size_t n; float sc = 1.f;
    switch (sel) {
        case 0: src = x;  dst = g_X;               n = (size_t)MT * DM; break;
        case 1: src = Wq; dst = g_Wt;              n = (size_t)DM * DM;
                sc = 0.125f * LOG2E; break;
        case 2: src = Wk; dst = g_Wt + (size_t)DM*DM;   n = (size_t)DM * DM; break;
        case 3: src = Wv; dst = g_Wt + (size_t)2*DM*DM; n = (size_t)DM * DM; break;
        default:src = Wo; dst = g_Wt + (size_t)3*DM*DM; n = (size_t)DM * DM; break;
    }
    const size_t i = ((size_t)blockIdx.x * 256 + threadIdx.x) * 4;
    if (i < n) {
        float4 v = *(const float4*)&src[i];
        *(__half2*)&dst[i]     = __floats2half2_rn(v.x * sc, v.y * sc);
        *(__half2*)&dst[i + 2] = __floats2half2_rn(v.z * sc, v.w * sc);
    }
}

// ---------------------------------------------------------------------------
// FP16 TC GEMM (unchanged from round 11): 128x128 CTA, 4 warps x 64x64,
// K-chunk 64, double-buffered cp.async, ldmatrix, PAD=72, 2 CTAs/SM.
// mode: 0 = fp16 out (q/k), 1 = fp32 + bias (final), 2 = per-head transposed V
// ---------------------------------------------------------------------------
#define KT 64
#define PAD 72
#define GSTG (128 * PAD)
#define GEMM_SMEM_BYTES (4 * GSTG * 2)        // 73728 B

__device__ __forceinline__ void gemm_stage(__half* As, __half* Bs,
                                           const __half* __restrict__ A,
                                           const __half* __restrict__ W,
                                           int m0, int n0, int k0, int tid)
{
#pragma unroll
    for (int rep = 0; rep < 8; rep++) {
        const int t = tid + rep * 128;
        const int row = t >> 3;
        const int seg = (t & 7) * 8;
        cpa16(&As[row * PAD + seg], &A[(size_t)(m0 + row) * DM + k0 + seg]);
        cpa16(&Bs[row * PAD + seg], &W[(size_t)(n0 + row) * DM + k0 + seg]);
    }
}

__device__ __forceinline__ void gemm128_tc(const __half* __restrict__ A,
                                           const __half* __restrict__ W,
                                           const float* __restrict__ bias,
                                           void* __restrict__ Cout,
                                           int mode)
{
    extern __shared__ __half smg[];
    __half* As = smg;
    __half* Bs = smg + 2 * GSTG;

    const int tid  = threadIdx.x;
    const int warp = tid >> 5, lane = tid & 31;
    const int wm = warp >> 1, wn = warp & 1;
    const int lg = lane >> 2, lt = lane & 3;
    const int m0 = blockIdx.y * 128;
    const int n0 = blockIdx.x * 128;

    const int arow = (lane & 7) + ((lane >> 3) & 1) * 8;
    const int acol = (lane >> 4) * 8;
    const int brow = (lane & 7) + (lane >> 4) * 8;
    const int bcol = ((lane >> 3) & 1) * 8;

    float acc[4][8][4];
#pragma unroll
    for (int i = 0; i < 4; i++)
#pragma unroll
        for (int j = 0; j < 8; j++)
#pragma unroll
            for (int e = 0; e < 4; e++) acc[i][j][e] = 0.f;

    gemm_stage(As, Bs, A, W, m0, n0, 0, tid);
    CPC();

    for (int k0 = 0; k0 < DM; k0 += KT) {
        const int cur = (k0 >> 6) & 1;
        __syncthreads();
        if (k0 + KT < DM)
            gemm_stage(As + (cur ^ 1) * GSTG, Bs + (cur ^ 1) * GSTG,
                       A, W, m0, n0, k0 + KT, tid);
        CPC();
        CPW1();
        __syncthreads();

        const __half* Ab = As + cur * GSTG;
        const __half* Bb = Bs + cur * GSTG;
#pragma unroll
        for (int ks = 0; ks < 4; ks++) {
            const int c = ks * 16;
            unsigned a[4][4], breg[16];
#pragma unroll
            for (int mt = 0; mt < 4; mt++)
                ldsm4(a[mt], &Ab[(wm * 64 + mt * 16 + arow) * PAD + acol + c]);
#pragma unroll
            for (int nb = 0; nb < 4; nb++)
                ldsm4(&breg[nb * 4],
                      &Bb[(wn * 64 + nb * 16 + brow) * PAD + bcol + c]);
#pragma unroll
            for (int mt = 0; mt < 4; mt++)
#pragma unroll
                for (int nt = 0; nt < 8; nt++)
                    mma_f16(acc[mt][nt], a[mt], &breg[nt * 2]);
        }
    }

    if (mode == 1) {
        float* C = (float*)Cout;
#pragma unroll
        for (int mt = 0; mt < 4; mt++) {
            const int r0 = m0 + wm * 64 + mt * 16 + lg;
#pragma unroll
            for (int nt = 0; nt < 8; nt++) {
                const int col = n0 + wn * 64 + nt * 8 + 2 * lt;
                const float b0 = bias[col], b1 = bias[col + 1];
                *(float2*)&C[(size_t)r0 * DM + col] =
                    make_float2(acc[mt][nt][0] + b0, acc[mt][nt][1] + b1);
                *(float2*)&C[(size_t)(r0 + 8) * DM + col] =
                    make_float2(acc[mt][nt][2] + b0, acc[mt][nt][3] + b1);
            }
        }
    } else if (mode == 0) {
        __half* C = (__half*)Cout;
#pragma unroll
        for (int mt = 0; mt < 4; mt++) {
            const int r0 = m0 + wm * 64 + mt * 16 + lg;
#pragma unroll
            for (int nt = 0; nt < 8; nt++) {
                const int col = n0 + wn * 64 + nt * 8 + 2 * lt;
                *(__half2*)&C[(size_t)r0 * DM + col] =
                    __floats2half2_rn(acc[mt][nt][0], acc[mt][nt][1]);
                *(__half2*)&C[(size_t)(r0 + 8) * DM + col] =
                    __floats2half2_rn(acc[mt][nt][2], acc[mt][nt][3]);
            }
        }
    } else {
        __half* C = (__half*)Cout;
#pragma unroll
        for (int mt = 0; mt < 4; mt++) {
            const int t0 = m0 + wm * 64 + mt * 16 + lg;
#pragma unroll
            for (int nt = 0; nt < 8; nt++) {
                const int col = n0 + wn * 64 + nt * 8 + 2 * lt;
                const int h = col >> 6, d = col & 63;
#pragma unroll
                for (int e = 0; e < 4; e++) {
                    const int t = t0 + (e >> 1) * 8;
                    const int dd = d + (e & 1);
                    const int b = t >> 11, s = t & 2047;
                    C[((size_t)(b * NH + h) * HD + dd) * SQ + s] =
                        __float2half(acc[mt][nt][e]);
                }
            }
        }
    }
}

__global__ __launch_bounds__(128, 2) void qkv_gemm_kernel()
{
    const __half* W; __half* C; int mode;
    if (blockIdx.z == 0)      { W = g_Wt;                   C = g_Q;  mode = 0; }
    else if (blockIdx.z == 1) { W = g_Wt + (size_t)DM*DM;   C = g_K;  mode = 0; }
    else                      { W = g_Wt + (size_t)2*DM*DM; C = g_Vt; mode = 2; }
    gemm128_tc(g_X, W, nullptr, C, mode);
}

__global__ __launch_bounds__(128, 2) void o_gemm_kernel(
    const float* __restrict__ bo, float* __restrict__ out)
{
    gemm128_tc(g_C, g_Wt + (size_t)3*DM*DM, bo, out, 1);
}

// ---------------------------------------------------------------------------
// Flash attention, FP16 TC + ldmatrix. Register-resident P, row-sum via
// ones-column of V, bias as accumulator init (paired float2 loads).
// 128 queries per CTA, 4 warps x 32 query rows. log2-domain softmax.
// ---------------------------------------------------------------------------
#define APAD 72
#define KTILE (64 * APAD)                       // K stage halves
#define VTILE (80 * APAD)                       // V stage halves (+ones/zeros)
#define KS_OFF 0
#define VT_OFF (2 * KTILE)                      // 9216
#define PS_OFF (VT_OFF + 2 * VTILE)             // 20736
#define ATTN_HALVES (PS_OFF + 128 * APAD)       // 29952
#define BS_BYTE_OFF (ATTN_HALVES * 2)           // 59904
#define ATTN_SMEM_BYTES (BS_BYTE_OFF + 2176 * 8)

__global__ __launch_bounds__(128, 2) void attn_kernel(const float* __restrict__ bt)
{
    extern __shared__ __half sm[];
    __half* Ks = sm + KS_OFF;     // [2][64][APAD] (key, d)
    __half* Vt = sm + VT_OFF;     // [2][80][APAD] (d, key); row 64 = ones
    __half* Ps = sm + PS_OFF;     // [128][APAD]  Q staging only
    float2* bsP = (float2*)((char*)sm + BS_BYTE_OFF);  // [2174] bias pairs

    const int tid  = threadIdx.x;
    const int warp = tid >> 5, lane = tid & 31;
    const int lg = lane >> 2, lt = lane & 3;
    const int bh = blockIdx.y;
    const int b = bh >> 4, h = bh & 15;
    const int q0 = blockIdx.x * 128;

    const __half* gK = g_K  + (size_t)b * SQ * DM + h * HD;
    const __half* gV = g_Vt + (size_t)(b * NH + h) * HD * SQ;

    const int arow = (lane & 7) + ((lane >> 3) & 1) * 8;
    const int acol = (lane >> 4) * 8;
    const int brow = (lane & 7) + (lane >> 4) * 8;
    const int bcol = ((lane >> 3) & 1) * 8;

    // bias pairs in log2 domain: bsP[j] = {bias[j], bias[j+1]}
    for (int j = tid; j < 2174; j += 128) {
        const float b0 = bt[(size_t)(q0 + j) * NH + h] * LOG2E;
        const float b1 = bt[(size_t)(q0 + j + 1) * NH + h] * LOG2E;
        bsP[j] = make_float2(b0, b1);
    }

    // static ones/zero rows 64..79 of both V stages
    {
        const __half one = __float2half(1.f);
        const __half zero = __float2half(0.f);
        for (int i = tid; i < 16 * APAD; i += 128) {
            const __half v = (i < APAD) ? one : zero;
            Vt[64 * APAD + i] = v;
            Vt[VTILE + 64 * APAD + i] = v;
        }
    }

    // stage Q row tid
    {
        const __half* src = g_Q + (size_t)(b * SQ + q0 + tid) * DM + h * HD;
#pragma unroll
        for (int rep = 0; rep < 8; rep++)
            *(uint4*)&Ps[tid * APAD + rep * 8] = *(const uint4*)&src[rep * 8];
    }
    __syncwarp();

    unsigned qf[2][4][4];
#pragma unroll
    for (int mt = 0; mt < 2; mt++)
#pragma unroll
        for (int ks = 0; ks < 4; ks++)
            ldsm4(qf[mt][ks],
                  &Ps[(warp * 32 + mt * 16 + arow) * APAD + acol + ks * 16]);
    __syncwarp();

    // prefetch tile 0
    {
#pragma unroll
        for (int rep = 0; rep < 4; rep++) {
            const int t = tid + rep * 128;
            const int r = t >> 3;
            const int c = (t & 7) * 8;
            cpa16(&Ks[r * APAD + c], &gK[(size_t)r * DM + c]);
            cpa16(&Vt[r * APAD + c], &gV[(size_t)r * SQ + c]);
        }
        CPC();
    }

    float mA[2] = {-1e30f, -1e30f}, mB[2] = {-1e30f, -1e30f};
    float o[2][9][4];
#pragma unroll
    for (int mt = 0; mt < 2; mt++)
#pragma unroll
        for (int nt = 0; nt < 9; nt++)
#pragma unroll
            for (int e = 0; e < 4; e++) o[mt][nt][e] = 0.f;

    for (int k0 = 0, t = 0; k0 < SQ; k0 += 64, t++) {
        const int cur = t & 1;
        __syncthreads();     // also publishes bsP/ones on first iteration
        if (k0 + 64 < SQ) {
            __half* Kn = Ks + (cur ^ 1) * KTILE;
            __half* Vn = Vt + (cur ^ 1) * VTILE;
#pragma unroll
            for (int rep = 0; rep < 4; rep++) {
                const int tt = tid + rep * 128;
                const int r = tt >> 3;
                const int c = (tt & 7) * 8;
                cpa16(&Kn[r * APAD + c], &gK[(size_t)(k0 + 64 + r) * DM + c]);
                cpa16(&Vn[r * APAD + c], &gV[(size_t)r * SQ + k0 + 64 + c]);
            }
        }
        CPC();
        CPW1();
        __syncthreads();

        const __half* Kb = Ks + cur * KTILE;
        const __half* Vb = Vt + cur * VTILE;

        // ---- S accumulators initialized with the relative bias
        float s[2][8][4];
#pragma unroll
        for (int mt = 0; mt < 2; mt++) {
            const int jb = warp * 32 + mt * 16 + lg + 2047 - k0;
#pragma unroll
            for (int nt = 0; nt < 8; nt++) {
                const int j = jb - (nt * 8 + 2 * lt) - 1;
                const float2 fA = bsP[j];
                const float2 fB = bsP[j + 8];
                s[mt][nt][0] = fA.y; s[mt][nt][1] = fA.x;
                s[mt][nt][2] = fB.y; s[mt][nt][3] = fB.x;
            }
        }

        // ---- S += Q' @ K^T (log2 domain)
#pragma unroll
        for (int ks = 0; ks < 4; ks++) {
            const int c = ks * 16;
            unsigned breg[16];
#pragma unroll
            for (int nb = 0; nb < 4; nb++)
                ldsm4(&breg[nb * 4], &Kb[(nb * 16 + brow) * APAD + bcol + c]);
#pragma unroll
            for (int nt = 0; nt < 8; nt++) {
                mma_f16(s[0][nt], qf[0][ks], &breg[nt * 2]);
                mma_f16(s[1][nt], qf[1][ks], &breg[nt * 2]);
            }
        }

        // ---- online softmax; P packed into registers (A-fragment layout)
        unsigned pu[2][8], pw[2][8];
#pragma unroll
        for (int mt = 0; mt < 2; mt++) {
            float mxA = -1e30f, mxB = -1e30f;
#pragma unroll
            for (int nt = 0; nt < 8; nt++) {
                mxA = fmaxf(mxA, fmaxf(s[mt][nt][0], s[mt][nt][1]));
                mxB = fmaxf(mxB, fmaxf(s[mt][nt][2], s[mt][nt][3]));
            }
#pragma unroll
            for (int off = 1; off <= 2; off <<= 1) {
                mxA = fmaxf(mxA, __shfl_xor_sync(0xffffffffu, mxA, off));
                mxB = fmaxf(mxB, __shfl_xor_sync(0xffffffffu, mxB, off));
            }
            const float mnA = fmaxf(mA[mt], mxA);
            const float mnB = fmaxf(mB[mt], mxB);
            const float crA = ex2(mA[mt] - mnA);
            const float crB = ex2(mB[mt] - mnB);
            mA[mt] = mnA; mB[mt] = mnB;
#pragma unroll
            for (int nt = 0; nt < 8; nt++) {
                const float e0 = ex2(s[mt][nt][0] - mnA);
                const float e1 = ex2(s[mt][nt][1] - mnA);
                const float e2 = ex2(s[mt][nt][2] - mnB);
                const float e3 = ex2(s[mt][nt][3] - mnB);
                pu[mt][nt] = packh2(e0, e1);
                pw[mt][nt] = packh2(e2, e3);
            }
#pragma unroll
            for (int nt = 0; nt < 9; nt++) {
                o[mt][nt][0] *= crA; o[mt][nt][1] *= crA;
                o[mt][nt][2] *= crB; o[mt][nt][3] *= crB;
            }
        }

        // ---- O += P @ V  (nt=8 is the ones-column -> row sums)
#pragma unroll
        for (int ks = 0; ks < 4; ks++) {
            const int c = ks * 16;
            unsigned breg[20];
#pragma unroll
            for (int nb = 0; nb < 5; nb++)
                ldsm4(&breg[nb * 4], &Vb[(nb * 16 + brow) * APAD + bcol + c]);
            const unsigned paA[4] = {pu[0][2*ks], pw[0][2*ks],
                                     pu[0][2*ks+1], pw[0][2*ks+1]};
            const unsigned paB[4] = {pu[1][2*ks], pw[1][2*ks],
                                     pu[1][2*ks+1], pw[1][2*ks+1]};
#pragma unroll
            for (int nt = 0; nt < 9; nt++) {
                mma_f16(o[0][nt], paA, &breg[nt * 2]);
                mma_f16(o[1][nt], paB, &breg[nt * 2]);
            }
        }
    }

    // ---- normalize (l lives in o[mt][8], col 64 -> lt==0 lanes) + write ctx
    const int lead = (lane >> 2) << 2;
#pragma unroll
    for (int mt = 0; mt < 2; mt++) {
        const float sumA = __shfl_sync(0xffffffffu, o[mt][8][0], lead);
        const float sumB = __shfl_sync(0xffffffffu, o[mt][8][2], lead);
        const float invA = 1.f / sumA;
        const float invB = 1.f / sumB;
        const int rA = warp * 32 + mt * 16 + lg;
        __half* dstA = g_C + (size_t)(b * SQ + q0 + rA) * DM + h * HD;
        __half* dstB = g_C + (size_t)(b * SQ + q0 + rA + 8) * DM + h * HD;
#pragma unroll
        for (int nt = 0; nt < 8; nt++) {
            const int col = nt * 8 + 2 * lt;
            *(__half2*)&dstA[col] =
                __floats2half2_rn(o[mt][nt][0] * invA, o[mt][nt][1] * invA);
            *(__half2*)&dstB[col] =
                __floats2half2_rn(o[mt][nt][2] * invB, o[mt][nt][3] * invB);
        }
    }
}

// ---------------------------------------------------------------------------
extern "C" void kernel_launch(void* const* d_in, const int* in_sizes, int n_in,
                              void* d_out, int out_size)
{
    (void)in_sizes; (void)n_in; (void)out_size;
    const float* x   = (const float*)d_in[0];
    const float* Wq  = (const float*)d_in[1];
    const float* Wk  = (const float*)d_in[2];
    const float* Wv  = (const float*)d_in[3];
    const float* Wo  = (const float*)d_in[4];
    const float* bo  = (const float*)d_in[5];
    const float* bt  = (const float*)d_in[6];
    float* out = (float*)d_out;

    // 0) fp16 prepass
    dim3 g0((MT * DM / 4 + 255) / 256, 5);
    prep_kernel<<<g0, 256>>>(x, Wq, Wk, Wv, Wo);

    // 1) QKV projections
    cudaFuncSetAttribute(qkv_gemm_kernel,
                         cudaFuncAttributeMaxDynamicSharedMemorySize,
                         GEMM_SMEM_BYTES);
    dim3 g1(DM / 128, MT / 128, 3);
    qkv_gemm_kernel<<<g1, 128, GEMM_SMEM_BYTES>>>();

    // 2) attention
    cudaFuncSetAttribute(attn_kernel,
                         cudaFuncAttributeMaxDynamicSharedMemorySize,
                         ATTN_SMEM_BYTES);
    dim3 g2(SQ / 128, BB * NH);
    attn_kernel<<<g2, 128, ATTN_SMEM_BYTES>>>(bt);

    // 3) output projection + bias
    cudaFuncSetAttribute(o_gemm_kernel,
                         cudaFuncAttributeMaxDynamicSharedMemorySize,
                         GEMM_SMEM_BYTES);
    dim3 g3(DM / 128, MT / 128);
    o_gemm_kernel<<<g3, 128, GEMM_SMEM_BYTES>>>(bo, out);
}

// round 16
// speedup vs baseline: 1.2772x; 1.0282x over previous
#include <cuda_runtime.h>
#include <cuda_fp16.h>
#include <cstdint>

#define DM 1024
#define NH 16
#define HD 64
#define SQ 2048
#define BB 4
#define MT (BB*SQ)   // 8192 rows total

// Scratch (no allocations allowed -> __device__ globals). All fp16.
__device__ __half g_X [(size_t)MT * DM];
__device__ __half g_Wt[(size_t)4 * DM * DM];     // Wq*log2e/8, Wk, Wv, Wo
__device__ __half g_Q [(size_t)MT * DM];         // q*log2e/8
__device__ __half g_K [(size_t)MT * DM];
__device__ __half g_Vt[(size_t)MT * DM];         // v^T per (b,h): [64][SQ]
__device__ __half g_C [(size_t)MT * DM];         // ctx

#define LOG2E 1.4426950408889634f

// ---------------------------------------------------------------------------
// helpers
// ---------------------------------------------------------------------------
__device__ __forceinline__ float ex2(float x)
{
    float y;
    asm("ex2.approx.ftz.f32 %0, %1;" : "=f"(y) : "f"(x));
    return y;
}
// pack (a,b) to half2, then exp2 both lanes with ONE MUFU issue
__device__ __forceinline__ unsigned h2ex2(float a, float b)
{
    __half2 h = __floats2half2_rn(a, b);
    unsigned r;
    asm("ex2.approx.f16x2 %0, %1;" : "=r"(r) : "r"(*(unsigned*)&h));
    return r;
}
__device__ __forceinline__ void mma_f16(float c[4], const unsigned a[4],
                                        const unsigned* b)
{
    asm volatile(
        "mma.sync.aligned.m16n8k16.row.col.f32.f16.f16.f32 "
        "{%0,%1,%2,%3},{%4,%5,%6,%7},{%8,%9},{%0,%1,%2,%3};"
        : "+f"(c[0]), "+f"(c[1]), "+f"(c[2]), "+f"(c[3])
        : "r"(a[0]), "r"(a[1]), "r"(a[2]), "r"(a[3]), "r"(b[0]), "r"(b[1]));
}
__device__ __forceinline__ void ldsm4(unsigned r[4], const __half* p)
{
    unsigned a = (unsigned)__cvta_generic_to_shared(p);
    asm volatile("ldmatrix.sync.aligned.m8n8.x4.shared.b16 {%0,%1,%2,%3}, [%4];"
                 : "=r"(r[0]), "=r"(r[1]), "=r"(r[2]), "=r"(r[3]) : "r"(a));
}
__device__ __forceinline__ void cpa16(void* smem_dst, const void* gsrc)
{
    unsigned s = (unsigned)__cvta_generic_to_shared(smem_dst);
    asm volatile("cp.async.cg.shared.global [%0], [%1], 16;\n" :: "r"(s), "l"(gsrc));
}
#define CPC()  asm volatile("cp.async.commit_group;\n")
#define CPW1() asm volatile("cp.async.wait_group 1;\n")

// ---------------------------------------------------------------------------
// prepass: fp32 -> fp16 (Wq scaled by log2e/8)
// ---------------------------------------------------------------------------
__global__ void prep_kernel(const float* __restrict__ x,
                            const float* __restrict__ Wq,
                            const float* __restrict__ Wk,
                            const float* __restrict__ Wv,
                            const float* __restrict__ Wo)
{
    const int sel = blockIdx.y;
    const float* src; __half* dst; size_t n; float sc = 1.f;
    switch (sel) {
        case 0: src = x;  dst = g_X;               n = (size_t)MT * DM; break;
        case 1: src = Wq; dst = g_Wt;              n = (size_t)DM * DM;
                sc = 0.125f * LOG2E; break;
        case 2: src = Wk; dst = g_Wt + (size_t)DM*DM;   n = (size_t)DM * DM; break;
        case 3: src = Wv; dst = g_Wt + (size_t)2*DM*DM; n = (size_t)DM * DM; break;
        default:src = Wo; dst = g_Wt + (size_t)3*DM*DM; n = (size_t)DM * DM; break;
    }
    const size_t i = ((size_t)blockIdx.x * 256 + threadIdx.x) * 4;
    if (i < n) {
        float4 v = *(const float4*)&src[i];
        *(__half2*)&dst[i]     = __floats2half2_rn(v.x * sc, v.y * sc);
        *(__half2*)&dst[i + 2] = __floats2half2_rn(v.z * sc, v.w * sc);
    }
}

// ---------------------------------------------------------------------------
// FP16 TC GEMM (unchanged): 128x128 CTA, 4 warps x 64x64, K-chunk 64,
// double-buffered cp.async, ldmatrix, PAD=72, 2 CTAs/SM.
// mode: 0 = fp16 out (q/k), 1 = fp32 + bias (final), 2 = per-head transposed V
// ---------------------------------------------------------------------------
#define KT 64
#define PAD 72
#define GSTG (128 * PAD)
#define GEMM_SMEM_BYTES (4 * GSTG * 2)        // 73728 B

__device__ __forceinline__ void gemm_stage(__half* As, __half* Bs,
                                           const __half* __restrict__ A,
                                           const __half* __restrict__ W,
                                           int m0, int n0, int k0, int tid)
{
#pragma unroll
    for (int rep = 0; rep < 8; rep++) {
        const int t = tid + rep * 128;
        const int row = t >> 3;
        const int seg = (t & 7) * 8;
        cpa16(&As[row * PAD + seg], &A[(size_t)(m0 + row) * DM + k0 + seg]);
        cpa16(&Bs[row * PAD + seg], &W[(size_t)(n0 + row) * DM + k0 + seg]);
    }
}

__device__ __forceinline__ void gemm128_tc(const __half* __restrict__ A,
                                           const __half* __restrict__ W,
                                           const float* __restrict__ bias,
                                           void* __restrict__ Cout,
                                           int mode)
{
    extern __shared__ __half smg[];
    __half* As = smg;
    __half* Bs = smg + 2 * GSTG;

    const int tid  = threadIdx.x;
    const int warp = tid >> 5, lane = tid & 31;
    const int wm = warp >> 1, wn = warp & 1;
    const int lg = lane >> 2, lt = lane & 3;
    const int m0 = blockIdx.y * 128;
    const int n0 = blockIdx.x * 128;

    const int arow = (lane & 7) + ((lane >> 3) & 1) * 8;
    const int acol = (lane >> 4) * 8;
    const int brow = (lane & 7) + (lane >> 4) * 8;
    const int bcol = ((lane >> 3) & 1) * 8;

    float acc[4][8][4];
#pragma unroll
    for (int i = 0; i < 4; i++)
#pragma unroll
        for (int j = 0; j < 8; j++)
#pragma unroll
            for (int e = 0; e < 4; e++) acc[i][j][e] = 0.f;

    gemm_stage(As, Bs, A, W, m0, n0, 0, tid);
    CPC();

    for (int k0 = 0; k0 < DM; k0 += KT) {
        const int cur = (k0 >> 6) & 1;
        __syncthreads();
        if (k0 + KT < DM)
            gemm_stage(As + (cur ^ 1) * GSTG, Bs + (cur ^ 1) * GSTG,
                       A, W, m0, n0, k0 + KT, tid);
        CPC();
        CPW1();
        __syncthreads();

        const __half* Ab = As + cur * GSTG;
        const __half* Bb = Bs + cur * GSTG;
#pragma unroll
        for (int ks = 0; ks < 4; ks++) {
            const int c = ks * 16;
            unsigned a[4][4], breg[16];
#pragma unroll
            for (int mt = 0; mt < 4; mt++)
                ldsm4(a[mt], &Ab[(wm * 64 + mt * 16 + arow) * PAD + acol + c]);
#pragma unroll
            for (int nb = 0; nb < 4; nb++)
                ldsm4(&breg[nb * 4],
                      &Bb[(wn * 64 + nb * 16 + brow) * PAD + bcol + c]);
#pragma unroll
            for (int mt = 0; mt < 4; mt++)
#pragma unroll
                for (int nt = 0; nt < 8; nt++)
                    mma_f16(acc[mt][nt], a[mt], &breg[nt * 2]);
        }
    }

    if (mode == 1) {
        float* C = (float*)Cout;
#pragma unroll
        for (int mt = 0; mt < 4; mt++) {
            const int r0 = m0 + wm * 64 + mt * 16 + lg;
#pragma unroll
            for (int nt = 0; nt < 8; nt++) {
                const int col = n0 + wn * 64 + nt * 8 + 2 * lt;
                const float b0 = bias[col], b1 = bias[col + 1];
                *(float2*)&C[(size_t)r0 * DM + col] =
                    make_float2(acc[mt][nt][0] + b0, acc[mt][nt][1] + b1);
                *(float2*)&C[(size_t)(r0 + 8) * DM + col] =
                    make_float2(acc[mt][nt][2] + b0, acc[mt][nt][3] + b1);
            }
        }
    } else if (mode == 0) {
        __half* C = (__half*)Cout;
#pragma unroll
        for (int mt = 0; mt < 4; mt++) {
            const int r0 = m0 + wm * 64 + mt * 16 + lg;
#pragma unroll
            for (int nt = 0; nt < 8; nt++) {
                const int col = n0 + wn * 64 + nt * 8 + 2 * lt;
                *(__half2*)&C[(size_t)r0 * DM + col] =
                    __floats2half2_rn(acc[mt][nt][0], acc[mt][nt][1]);
                *(__half2*)&C[(size_t)(r0 + 8) * DM + col] =
                    __floats2half2_rn(acc[mt][nt][2], acc[mt][nt][3]);
            }
        }
    } else {
        __half* C = (__half*)Cout;
#pragma unroll
        for (int mt = 0; mt < 4; mt++) {
            const int t0 = m0 + wm * 64 + mt * 16 + lg;
#pragma unroll
            for (int nt = 0; nt < 8; nt++) {
                const int col = n0 + wn * 64 + nt * 8 + 2 * lt;
                const int h = col >> 6, d = col & 63;
#pragma unroll
                for (int e = 0; e < 4; e++) {
                    const int t = t0 + (e >> 1) * 8;
                    const int dd = d + (e & 1);
                    const int b = t >> 11, s = t & 2047;
                    C[((size_t)(b * NH + h) * HD + dd) * SQ + s] =
                        __float2half(acc[mt][nt][e]);
                }
            }
        }
    }
}

__global__ __launch_bounds__(128, 2) void qkv_gemm_kernel()
{
    const __half* W; __half* C; int mode;
    if (blockIdx.z == 0)      { W = g_Wt;                   C = g_Q;  mode = 0; }
    else if (blockIdx.z == 1) { W = g_Wt + (size_t)DM*DM;   C = g_K;  mode = 0; }
    else                      { W = g_Wt + (size_t)2*DM*DM; C = g_Vt; mode = 2; }
    gemm128_tc(g_X, W, nullptr, C, mode);
}

__global__ __launch_bounds__(128, 2) void o_gemm_kernel(
    const float* __restrict__ bo, float* __restrict__ out)
{
    gemm128_tc(g_C, g_Wt + (size_t)3*DM*DM, bo, out, 1);
}

// ---------------------------------------------------------------------------
// Flash attention, FP16 TC + ldmatrix. Register-resident P, row-sum via
// ones-column of V, bias as accumulator init, f16x2 exp (half the MUFU).
// 128 queries per CTA, 4 warps x 32 query rows. log2-domain softmax.
// ---------------------------------------------------------------------------
#define APAD 72
#define KTILE (64 * APAD)                       // K stage halves
#define VTILE (80 * APAD)                       // V stage halves (+ones/zeros)
#define KS_OFF 0
#define VT_OFF (2 * KTILE)                      // 9216
#define PS_OFF (VT_OFF + 2 * VTILE)             // 20736
#define ATTN_HALVES (PS_OFF + 128 * APAD)       // 29952
#define BS_BYTE_OFF (ATTN_HALVES * 2)           // 59904
#define ATTN_SMEM_BYTES (BS_BYTE_OFF + 2176 * 8)

__global__ __launch_bounds__(128, 2) void attn_kernel(const float* __restrict__ bt)
{
    extern __shared__ __half sm[];
    __half* Ks = sm + KS_OFF;     // [2][64][APAD] (key, d)
    __half* Vt = sm + VT_OFF;     // [2][80][APAD] (d, key); row 64 = ones
    __half* Ps = sm + PS_OFF;     // [128][APAD]  Q staging only
    float2* bsP = (float2*)((char*)sm + BS_BYTE_OFF);  // [2174] bias pairs

    const int tid  = threadIdx.x;
    const int warp = tid >> 5, lane = tid & 31;
    const int lg = lane >> 2, lt = lane & 3;
    const int bh = blockIdx.y;
    const int b = bh >> 4, h = bh & 15;
    const int q0 = blockIdx.x * 128;

    const __half* gK = g_K  + (size_t)b * SQ * DM + h * HD;
    const __half* gV = g_Vt + (size_t)(b * NH + h) * HD * SQ;

    const int arow = (lane & 7) + ((lane >> 3) & 1) * 8;
    const int acol = (lane >> 4) * 8;
    const int brow = (lane & 7) + (lane >> 4) * 8;
    const int bcol = ((lane >> 3) & 1) * 8;

    // bias pairs in log2 domain: bsP[j] = {bias[j], bias[j+1]}
    for (int j = tid; j < 2174; j += 128) {
        const float b0 = bt[(size_t)(q0 + j) * NH + h] * LOG2E;
        const float b1 = bt[(size_t)(q0 + j + 1) * NH + h] * LOG2E;
        bsP[j] = make_float2(b0, b1);
    }

    // static ones/zero rows 64..79 of both V stages
    {
        const __half one = __float2half(1.f);
        const __half zero = __float2half(0.f);
        for (int i = tid; i < 16 * APAD; i += 128) {
            const __half v = (i < APAD) ? one : zero;
            Vt[64 * APAD + i] = v;
            Vt[VTILE + 64 * APAD + i] = v;
        }
    }

    // stage Q row tid
    {
        const __half* src = g_Q + (size_t)(b * SQ + q0 + tid) * DM + h * HD;
#pragma unroll
        for (int rep = 0; rep < 8; rep++)
            *(uint4*)&Ps[tid * APAD + rep * 8] = *(const uint4*)&src[rep * 8];
    }
    __syncwarp();

    unsigned qf[2][4][4];
#pragma unroll
    for (int mt = 0; mt < 2; mt++)
#pragma unroll
        for (int ks = 0; ks < 4; ks++)
            ldsm4(qf[mt][ks],
                  &Ps[(warp * 32 + mt * 16 + arow) * APAD + acol + ks * 16]);
    __syncwarp();

    // prefetch tile 0
    {
#pragma unroll
        for (int rep = 0; rep < 4; rep++) {
            const int t = tid + rep * 128;
            const int r = t >> 3;
            const int c = (t & 7) * 8;
            cpa16(&Ks[r * APAD + c], &gK[(size_t)r * DM + c]);
            cpa16(&Vt[r * APAD + c], &gV[(size_t)r * SQ + c]);
        }
        CPC();
    }

    float mA[2] = {-1e30f, -1e30f}, mB[2] = {-1e30f, -1e30f};
    float o[2][9][4];
#pragma unroll
    for (int mt = 0; mt < 2; mt++)
#pragma unroll
        for (int nt = 0; nt < 9; nt++)
#pragma unroll
            for (int e = 0; e < 4; e++) o[mt][nt][e] = 0.f;

    for (int k0 = 0, t = 0; k0 < SQ; k0 += 64, t++) {
        const int cur = t & 1;
        __syncthreads();     // also publishes bsP/ones on first iteration
        if (k0 + 64 < SQ) {
            __half* Kn = Ks + (cur ^ 1) * KTILE;
            __half* Vn = Vt + (cur ^ 1) * VTILE;
#pragma unroll
            for (int rep = 0; rep < 4; rep++) {
                const int tt = tid + rep * 128;
                const int r = tt >> 3;
                const int c = (tt & 7) * 8;
                cpa16(&Kn[r * APAD + c], &gK[(size_t)(k0 + 64 + r) * DM + c]);
                cpa16(&Vn[r * APAD + c], &gV[(size_t)r * SQ + k0 + 64 + c]);
            }
        }
        CPC();
        CPW1();
        __syncthreads();

        const __half* Kb = Ks + cur * KTILE;
        const __half* Vb = Vt + cur * VTILE;

        // ---- S accumulators initialized with the relative bias
        float s[2][8][4];
#pragma unroll
        for (int mt = 0; mt < 2; mt++) {
            const int jb = warp * 32 + mt * 16 + lg + 2047 - k0;
#pragma unroll
            for (int nt = 0; nt < 8; nt++) {
                const int j = jb - (nt * 8 + 2 * lt) - 1;
                const float2 fA = bsP[j];
                const float2 fB = bsP[j + 8];
                s[mt][nt][0] = fA.y; s[mt][nt][1] = fA.x;
                s[mt][nt][2] = fB.y; s[mt][nt][3] = fB.x;
            }
        }

        // ---- S += Q' @ K^T (log2 domain)
#pragma unroll
        for (int ks = 0; ks < 4; ks++) {
            const int c = ks * 16;
            unsigned breg[16];
#pragma unroll
            for (int nb = 0; nb < 4; nb++)
                ldsm4(&breg[nb * 4], &Kb[(nb * 16 + brow) * APAD + bcol + c]);
#pragma unroll
            for (int nt = 0; nt < 8; nt++) {
                mma_f16(s[0][nt], qf[0][ks], &breg[nt * 2]);
                mma_f16(s[1][nt], qf[1][ks], &breg[nt * 2]);
            }
        }

        // ---- online softmax; exp via f16x2 MUFU, P packed in registers
        unsigned pu[2][8], pw[2][8];
#pragma unroll
        for (int mt = 0; mt < 2; mt++) {
            float mxA = -1e30f, mxB = -1e30f;
#pragma unroll
            for (int nt = 0; nt < 8; nt++) {
                mxA = fmaxf(mxA, fmaxf(s[mt][nt][0], s[mt][nt][1]));
                mxB = fmaxf(mxB, fmaxf(s[mt][nt][2], s[mt][nt][3]));
            }
#pragma unroll
            for (int off = 1; off <= 2; off <<= 1) {
                mxA = fmaxf(mxA, __shfl_xor_sync(0xffffffffu, mxA, off));
                mxB = fmaxf(mxB, __shfl_xor_sync(0xffffffffu, mxB, off));
            }
            const float mnA = fmaxf(mA[mt], mxA);
            const float mnB = fmaxf(mB[mt], mxB);
            const float crA = ex2(mA[mt] - mnA);
            const float crB = ex2(mB[mt] - mnB);
            mA[mt] = mnA; mB[mt] = mnB;
#pragma unroll
            for (int nt = 0; nt < 8; nt++) {
                pu[mt][nt] = h2ex2(s[mt][nt][0] - mnA, s[mt][nt][1] - mnA);
                pw[mt][nt] = h2ex2(s[mt][nt][2] - mnB, s[mt][nt][3] - mnB);
            }
#pragma unroll
            for (int nt = 0; nt < 9; nt++) {
                o[mt][nt][0] *= crA; o[mt][nt][1] *= crA;
                o[mt][nt][2] *= crB; o[mt][nt][3] *= crB;
            }
        }

        // ---- O += P @ V  (nt=8 is the ones-column -> row sums)
#pragma unroll
        for (int ks = 0; ks < 4; ks++) {
            const int c = ks * 16;
            unsigned breg[20];
#pragma unroll
            for (int nb = 0; nb < 5; nb++)
                ldsm4(&breg[nb * 4], &Vb[(nb * 16 + brow) * APAD + bcol + c]);
            const unsigned paA[4] = {pu[0][2*ks], pw[0][2*ks],
                                     pu[0][2*ks+1], pw[0][2*ks+1]};
            const unsigned paB[4] = {pu[1][2*ks], pw[1][2*ks],
                                     pu[1][2*ks+1], pw[1][2*ks+1]};
#pragma unroll
            for (int nt = 0; nt < 9; nt++) {
                mma_f16(o[0][nt], paA, &breg[nt * 2]);
                mma_f16(o[1][nt], paB, &breg[nt * 2]);
            }
        }
    }

    // ---- normalize (l lives in o[mt][8], col 64 -> lt==0 lanes) + write ctx
    const int lead = (lane >> 2) << 2;
#pragma unroll
    for (int mt = 0; mt < 2; mt++) {
        const float sumA = __shfl_sync(0xffffffffu, o[mt][8][0], lead);
        const float sumB = __shfl_sync(0xffffffffu, o[mt][8][2], lead);
        const float invA = 1.f / sumA;
        const float invB = 1.f / sumB;
        const int rA = warp * 32 + mt * 16 + lg;
        __half* dstA = g_C + (size_t)(b * SQ + q0 + rA) * DM + h * HD;
        __half* dstB = g_C + (size_t)(b * SQ + q0 + rA + 8) * DM + h * HD;
#pragma unroll
        for (int nt = 0; nt < 8; nt++) {
            const int col = nt * 8 + 2 * lt;
            *(__half2*)&dstA[col] =
                __floats2half2_rn(o[mt][nt][0] * invA, o[mt][nt][1] * invA);
            *(__half2*)&dstB[col] =
                __floats2half2_rn(o[mt][nt][2] * invB, o[mt][nt][3] * invB);
        }
    }
}

// ---------------------------------------------------------------------------
extern "C" void kernel_launch(void* const* d_in, const int* in_sizes, int n_in,
                              void* d_out, int out_size)
{
    (void)in_sizes; (void)n_in; (void)out_size;
    const float* x   = (const float*)d_in[0];
    const float* Wq  = (const float*)d_in[1];
    const float* Wk  = (const float*)d_in[2];
    const float* Wv  = (const float*)d_in[3];
    const float* Wo  = (const float*)d_in[4];
    const float* bo  = (const float*)d_in[5];
    const float* bt  = (const float*)d_in[6];
    float* out = (float*)d_out;

    // 0) fp16 prepass
    dim3 g0((MT * DM / 4 + 255) / 256, 5);
    prep_kernel<<<g0, 256>>>(x, Wq, Wk, Wv, Wo);

    // 1) QKV projections
    cudaFuncSetAttribute(qkv_gemm_kernel,
                         cudaFuncAttributeMaxDynamicSharedMemorySize,
                         GEMM_SMEM_BYTES);
    dim3 g1(DM / 128, MT / 128, 3);
    qkv_gemm_kernel<<<g1, 128, GEMM_SMEM_BYTES>>>();

    // 2) attention
    cudaFuncSetAttribute(attn_kernel,
                         cudaFuncAttributeMaxDynamicSharedMemorySize,
                         ATTN_SMEM_BYTES);
    dim3 g2(SQ / 128, BB * NH);
    attn_kernel<<<g2, 128, ATTN_SMEM_BYTES>>>(bt);

    // 3) output projection + bias
    cudaFuncSetAttribute(o_gemm_kernel,
                         cudaFuncAttributeMaxDynamicSharedMemorySize,
                         GEMM_SMEM_BYTES);
    dim3 g3(DM / 128, MT / 128);
    o_gemm_kernel<<<g3, 128, GEMM_SMEM_BYTES>>>(bo, out);
}